// round 17
// baseline (speedup 1.0000x reference)
#include <cuda_runtime.h>
#include <math.h>

#define NN 4096
#define EE 65536
#define DD 64

// ---------------- static device scratch ----------------
__device__ int                g_cnt_s[NN];
__device__ int                g_cnt_d[NN];
__device__ int                g_rp_s[NN + 1];
__device__ int                g_rp_d[NN + 1];
__device__ unsigned           g_cs[EE];        // out-edges of n: packed (e<<12)|dst
__device__ unsigned           g_cd[EE];        // in-edges of n:  packed (e<<12)|src
__device__ unsigned long long g_keys[NN];
__device__ unsigned short     g_order[NN];
__device__ int                g_rem[NN];
__device__ int                g_h[NN];
__device__ int                g_rel[NN];
__device__ int                g_K[1];

// ============ FROZEN SCORE PATH (bit-exact vs reference; DO NOT TOUCH) ======
static __device__ __forceinline__ float xla_tanh_fma(float v) {
    float ax = fabsf(v);
    float xc = fminf(fmaxf(v, -7.99881172180175781f), 7.99881172180175781f);
    float x2 = __fmul_rn(xc, xc);
    float p = -2.76076847742355e-16f;
    p = __fmaf_rn(p, x2, 2.00018790482477e-13f);
    p = __fmaf_rn(p, x2, -8.60467152213735e-11f);
    p = __fmaf_rn(p, x2, 5.12229709037114e-08f);
    p = __fmaf_rn(p, x2, 1.48572235717979e-05f);
    p = __fmaf_rn(p, x2, 6.37261928875436e-04f);
    p = __fmaf_rn(p, x2, 4.89352455891786e-03f);
    p = __fmul_rn(p, xc);
    float q = 1.19825839466702e-06f;
    q = __fmaf_rn(q, x2, 1.18534705686654e-04f);
    q = __fmaf_rn(q, x2, 2.26843463243900e-03f);
    q = __fmaf_rn(q, x2, 4.89352518554385e-03f);
    float r = __fdiv_rn(p, q);
    return (ax < 0.0004f) ? v : r;
}

static __device__ __forceinline__ float eigen_gemv4_dot(const float* __restrict__ a,
                                                        const float* __restrict__ w) {
    float t0[4] = {0.f, 0.f, 0.f, 0.f};
    float t1[4] = {0.f, 0.f, 0.f, 0.f};
    float t2[4] = {0.f, 0.f, 0.f, 0.f};
    float t3[4] = {0.f, 0.f, 0.f, 0.f};
#pragma unroll
    for (int i = 0; i < DD / 16; i++) {
#pragma unroll
        for (int l = 0; l < 4; l++) {
            t0[l] = __fmaf_rn(a[16 * i + 0 + l],  w[16 * i + 0 + l],  t0[l]);
            t1[l] = __fmaf_rn(a[16 * i + 4 + l],  w[16 * i + 4 + l],  t1[l]);
            t2[l] = __fmaf_rn(a[16 * i + 8 + l],  w[16 * i + 8 + l],  t2[l]);
            t3[l] = __fmaf_rn(a[16 * i + 12 + l], w[16 * i + 12 + l], t3[l]);
        }
    }
    float v[4];
#pragma unroll
    for (int l = 0; l < 4; l++)
        v[l] = __fadd_rn(__fadd_rn(t0[l], t1[l]), __fadd_rn(t2[l], t3[l]));
    return __fadd_rn(__fadd_rn(v[0], v[2]), __fadd_rn(v[1], v[3]));
}
// ============================================================================

__global__ void k_count(const int* __restrict__ ei) {
    int e = blockIdx.x * blockDim.x + threadIdx.x;
    if (e >= EE) return;
    atomicAdd(&g_cnt_s[ei[e]], 1);
    atomicAdd(&g_cnt_d[ei[EE + e]], 1);
}

// hierarchical scan: 1024 threads x 4 elems, 3 barriers per array
__global__ void __launch_bounds__(1024, 1) k_scan_deg2() {
    __shared__ int wsum[32];
    int t = threadIdx.x, lane = t & 31, wid = t >> 5;
    for (int pass = 0; pass < 2; pass++) {
        int* cnt = pass ? g_cnt_d : g_cnt_s;
        int* rp  = pass ? g_rp_d  : g_rp_s;
        int base = t * 4;
        int c0 = cnt[base], c1 = cnt[base + 1], c2 = cnt[base + 2], c3 = cnt[base + 3];
        int p1 = c0 + c1, p2 = p1 + c2, p3 = p2 + c3;
        int s = p3, v = s;
        for (int o = 1; o < 32; o <<= 1) {
            int tv = __shfl_up_sync(0xFFFFFFFF, v, o);
            if (lane >= o) v += tv;
        }
        if (lane == 31) wsum[wid] = v;
        __syncthreads();
        if (wid == 0) {
            int vv = wsum[lane];
            for (int o = 1; o < 32; o <<= 1) {
                int tv = __shfl_up_sync(0xFFFFFFFF, vv, o);
                if (lane >= o) vv += tv;
            }
            wsum[lane] = vv;
        }
        __syncthreads();
        int off = (wid ? wsum[wid - 1] : 0) + (v - s);
        rp[base + 1] = off + c0; rp[base + 2] = off + p1;
        rp[base + 3] = off + p2; rp[base + 4] = off + p3;
        cnt[base] = 0; cnt[base + 1] = 0; cnt[base + 2] = 0; cnt[base + 3] = 0;
        if (t == 0) rp[0] = 0;
        __syncthreads();
    }
}

__global__ void k_fill(const int* __restrict__ ei) {
    int e = blockIdx.x * blockDim.x + threadIdx.x;
    if (e >= EE) return;
    int s = ei[e], d = ei[EE + e];
    int ps = g_rp_s[s] + atomicAdd(&g_cnt_s[s], 1);
    g_cs[ps] = ((unsigned)e << 12) | (unsigned)d;
    int pd = g_rp_d[d] + atomicAdd(&g_cnt_d[d], 1);
    g_cd[pd] = ((unsigned)e << 12) | (unsigned)s;
}

// fused: sort in-row by edge id + strict sequential agg + FROZEN score/key.
// Also re-zeroes the count arrays for the next graph replay.
__global__ void __launch_bounds__(DD, 1) k_sortagg(const float* __restrict__ x,
                                                   const float* __restrict__ w_rel,
                                                   const float* __restrict__ w_root,
                                                   const float* __restrict__ b) {
    __shared__ unsigned row[256];
    __shared__ float srow[DD];
    int n = blockIdx.x, t = threadIdx.x;
    int lo = g_rp_d[n];
    int deg = g_rp_d[n + 1] - lo;
    float acc = 0.f;
    if (deg <= 256) {
        for (int i = t; i < deg; i += DD) row[i] = g_cd[lo + i];
        __syncthreads();
        if (t == 0) {
            for (int i = 1; i < deg; i++) {
                unsigned v = row[i]; int j = i - 1;
                while (j >= 0 && row[j] > v) { row[j + 1] = row[j]; j--; }
                row[j + 1] = v;
            }
        }
        __syncthreads();
        for (int i = 0; i < deg; i++)
            acc = __fadd_rn(acc, x[(int)(row[i] & 0xFFFu) * DD + t]);
    } else {  // correctness fallback (never hit for this data)
        if (t == 0) {
            for (int i = lo + 1; i < lo + deg; i++) {
                unsigned v = g_cd[i]; int j = i - 1;
                while (j >= lo && g_cd[j] > v) { g_cd[j + 1] = g_cd[j]; j--; }
                g_cd[j + 1] = v;
            }
        }
        __syncthreads();
        for (int i = 0; i < deg; i++)
            acc = __fadd_rn(acc, x[(int)(g_cd[lo + i] & 0xFFFu) * DD + t]);
    }
    srow[t] = acc;
    if (t == 0) { g_cnt_s[n] = 0; g_cnt_d[n] = 0; }   // replay hygiene
    __syncthreads();
    if (t == 0) {
        float z1 = eigen_gemv4_dot(srow, w_rel);
        float z2 = eigen_gemv4_dot(&x[n * DD], w_root);
        float z = __fadd_rn(__fadd_rn(z1, z2), b[0]);
        float s = xla_tanh_fma(z);
        unsigned sb = __float_as_uint(s);
        unsigned m = sb ^ ((sb & 0x80000000u) ? 0xFFFFFFFFu : 0x80000000u);
        g_keys[n] = (((unsigned long long)(~m)) << 32) | (unsigned)n;
    }
}

__global__ void __launch_bounds__(1024, 1) k_sort() {
    __shared__ unsigned long long k[NN];
    int t = threadIdx.x;
    for (int i = t; i < NN; i += 1024) k[i] = g_keys[i];
    __syncthreads();
    for (int size = 2; size <= NN; size <<= 1) {
        for (int stride = size >> 1; stride > 0; stride >>= 1) {
            for (int i = t; i < NN / 2; i += 1024) {
                int lo = 2 * i - (i & (stride - 1));
                int hi = lo + stride;
                bool asc = ((lo & size) == 0);
                unsigned long long a = k[lo], b = k[hi];
                if ((a > b) == asc) { k[lo] = b; k[hi] = a; }
            }
            __syncthreads();
        }
    }
    for (int i = t; i < NN; i += 1024) g_order[i] = (unsigned short)(k[i] & 0xFFFFULL);
}

// ---------- merge: single warp, packed ord64 slots, no ballots in step body
// ord64[pos] lo32 = node | skipbit(bit31); hi32 = rs | (deg<<17) (static).
// w[i]: [11:0] rep, CENB center, ABSB absorbed. absorbable(d) <=> w[d]==d.
// Self-loop: n absorbable at own step by construction -> unconditional store;
// centerhood via lane0 atomicOr(w[n],CENB) (ATOMS RMW indivisible vs store;
// both orders end at the correct word). All writes idempotent -> no dedupe.
#define CENB 0x10000u
#define ABSB 0x20000u
#define SM_ORD   0                                   // u64[NN]  (8-aligned)
#define SM_W     (SM_ORD + 8 * NN)                   // u32[NN]
#define SM_COLS  (SM_W + 4 * NN)                     // u16[EE]  (offset 49152, 8-aligned)
#define SM_INV   (SM_COLS + 2 * EE)                  // u16[NN]
#define SMEM_MERGE (SM_INV + 2 * NN)

__global__ void __launch_bounds__(32, 1) k_merge() {
    extern __shared__ char smx[];
    unsigned long long* ord64 = (unsigned long long*)(smx + SM_ORD);
    unsigned*           w     = (unsigned*)(smx + SM_W);
    unsigned short*     cols  = (unsigned short*)(smx + SM_COLS);
    unsigned short*     inv   = (unsigned short*)(smx + SM_INV);

    int lane = threadIdx.x;
    for (int pos = lane; pos < NN; pos += 32) {
        int node = g_order[pos];
        int rs = g_rp_s[node];
        int deg = g_rp_s[node + 1] - rs;
        ord64[pos] = (unsigned long long)(unsigned)node
                   | ((unsigned long long)((unsigned)rs | ((unsigned)deg << 17)) << 32);
        inv[node] = (unsigned short)pos;
        w[node] = (unsigned)node;
    }
    const uint4* cs4 = (const uint4*)g_cs;
    for (int i = lane; i < EE / 4; i += 32) {
        uint4 v = cs4[i];
        unsigned long long pk =
            (unsigned long long)(v.x & 0xFFFu)
          | ((unsigned long long)(v.y & 0xFFFu) << 16)
          | ((unsigned long long)(v.z & 0xFFFu) << 32)
          | ((unsigned long long)(v.w & 0xFFFu) << 48);
        *(unsigned long long*)(cols + 4 * i) = pk;
    }
    __syncwarp();

    int step = 0;
    while (step < NN) {
        int n = -1, rs = 0, deg = 0;
        for (;;) {
            int idx = step + lane;
            unsigned long long ov = (idx < NN) ? ord64[idx] : 0x80000000ULL;
            unsigned lo32 = (unsigned)ov;
            unsigned act = ~__ballot_sync(0xFFFFFFFF, (lo32 & 0x80000000u) != 0);
            if (act) {
                int win = __ffs(act) - 1;
                step += win;
                unsigned hi32 = (unsigned)(ov >> 32);
                n = __shfl_sync(0xFFFFFFFF, (int)lo32, win) & 0xFFF;
                unsigned h2 = __shfl_sync(0xFFFFFFFF, hi32, win);
                rs = (int)(h2 & 0x1FFFFu);
                deg = (int)(h2 >> 17);
                break;
            }
            step += 32;
            if (step >= NN) break;
        }
        if (n < 0 || step >= NN) break;
        if (lane == 0) atomicOr(&w[n], CENB);
        for (int e = rs + lane; e < rs + deg; e += 32) {
            int d = cols[e];
            if (d == n) {
                w[n] = (unsigned)n | CENB | ABSB;          // self-loop: always absorbable
            } else if (w[d] == (unsigned)d) {
                w[d] = (unsigned)n | CENB | ABSB;
                *(unsigned*)((char*)smx + SM_ORD + 8 * (int)inv[d]) = 0x80000000u; // skip flag
            }
        }
        __syncwarp();
        step++;
    }

    // tail: prefix scan of kept = !(w & ABSB) -> g_rel, g_K; export rem/h
    const int chunk = NN / 32;
    int base = lane * chunk;
    int s = 0;
    for (int i = 0; i < chunk; i++) s += (w[base + i] & ABSB) ? 0 : 1;
    int v = s;
    for (int o = 1; o < 32; o <<= 1) {
        int tv = __shfl_up_sync(0xFFFFFFFF, v, o);
        if (lane >= o) v += tv;
    }
    int run = v - s;
    for (int i = 0; i < chunk; i++) {
        int kept = (w[base + i] & ABSB) ? 0 : 1;
        run += kept;
        g_rel[base + i] = run - 1;
        g_rem[base + i] = kept;
        g_h[base + i] = (int)(w[base + i] & 0xFFFu);
    }
    if (lane == 31) g_K[0] = v;
}

// output (float32): x_pooled[NN*DD] | new_edge_index[2*EE] | batch_pooled[NN] | perm[NN]
__global__ void k_fill_out(const float* __restrict__ x, const int* __restrict__ batch,
                           float* __restrict__ out, int out_size) {
    int n = blockIdx.x, t = threadIdx.x;
    int K = g_K[0];
    int ob = NN * DD + 2 * EE;
    int op = ob + NN;
    if (g_rem[n]) {
        int k = g_rel[n];
        int idx = k * DD + t;
        if (idx < out_size) out[idx] = x[n * DD + t];
        if (t == 0) {
            if (ob + k < out_size) out[ob + k] = (float)batch[n];
            if (op + k < out_size) out[op + k] = (float)n;
        }
    }
    if (n >= K) {
        int idx = n * DD + t;
        if (idx < out_size) out[idx] = 0.f;
        if (t == 0) {
            if (ob + n < out_size) out[ob + n] = -1.f;
            if (op + n < out_size) out[op + n] = -1.f;
        }
    }
}

__global__ void k_pool_add(const float* __restrict__ x, float* __restrict__ out,
                           int out_size) {
    int r = blockIdx.x, t = threadIdx.x;
    if (g_rem[r]) return;           // not absorbed
    int c = g_h[r];
    if (!g_rem[c]) return;          // absorber not kept (self-loop center)
    int idx = g_rel[c] * DD + t;
    if (idx < out_size) atomicAdd(&out[idx], x[r * DD + t]);
}

__global__ void k_fill_edges(const int* __restrict__ ei, float* __restrict__ out, int out_size) {
    int e = blockIdx.x * blockDim.x + threadIdx.x;
    if (e >= EE) return;
    int s = ei[e], d = ei[EE + e];
    bool v = g_rem[s] && g_rem[d];
    int oe = NN * DD;
    if (oe + e < out_size)      out[oe + e]      = v ? (float)g_rel[s] : -1.f;
    if (oe + EE + e < out_size) out[oe + EE + e] = v ? (float)g_rel[d] : -1.f;
}

extern "C" void kernel_launch(void* const* d_in, const int* in_sizes, int n_in,
                              void* d_out, int out_size) {
    const float* x      = (const float*)d_in[0];
    const int*   ei     = (const int*)d_in[1];
    const int*   batch  = (const int*)d_in[2];
    const float* w_rel  = (const float*)d_in[3];
    const float* w_root = (const float*)d_in[4];
    const float* b      = (const float*)d_in[5];
    float* out = (float*)d_out;

    cudaFuncSetAttribute(k_merge, cudaFuncAttributeMaxDynamicSharedMemorySize, SMEM_MERGE);

    k_count<<<EE / 256, 256>>>(ei);
    k_scan_deg2<<<1, 1024>>>();
    k_fill<<<EE / 256, 256>>>(ei);
    k_sortagg<<<NN, DD>>>(x, w_rel, w_root, b);
    k_sort<<<1, 1024>>>();
    k_merge<<<1, 32, SMEM_MERGE>>>();
    k_fill_out<<<NN, DD>>>(x, batch, out, out_size);
    k_pool_add<<<NN, DD>>>(x, out, out_size);
    k_fill_edges<<<EE / 256, 256>>>(ei, out, out_size);
}